// round 4
// baseline (speedup 1.0000x reference)
#include <cuda_runtime.h>
#include <math_constants.h>

#define BATCH   8
#define NSHAPE  8192
#define NSKEL   2048

#define NB      256
#define XMIN    (-6.0f)
#define STEP    0.046875f        /* 12/256 */
#define INVSTEP 21.3333333f

#define NESH    (NSHAPE / 2)     /* 4096 packed entries */
#define NESK    (NSKEL / 2)      /* 1024 */

#define PREPTHR 256
#define SCANTHR 128
#define CHUNK   512              /* buffer entries per pass */
#define S1B     (BATCH * NSHAPE / SCANTHR)   /* 512 */
#define S2B     (BATCH * NSKEL  / SCANTHR)   /* 128 */
#define NBLK    (S1B + S2B)                  /* 640 */

// Sorted SoA (pair-packed via float2), CDFs, scalar state. All rewritten each
// call (prep kernel) or self-resetting (accum/done) => graph-replay safe.
__device__ float2 g_shx[BATCH][NESH], g_shy[BATCH][NESH], g_shz[BATCH][NESH], g_shn[BATCH][NESH];
__device__ float2 g_skx[BATCH][NESK], g_sky[BATCH][NESK], g_skz[BATCH][NESK], g_skn[BATCH][NESK];
__device__ unsigned int g_cdfSh[BATCH][NB + 1];
__device__ unsigned int g_cdfSk[BATCH][NB + 1];
__device__ float        g_accum;
__device__ unsigned int g_done;

// ---------------------------------------------------------------------------
__device__ __forceinline__ int xbin(float x) {
    int b = (int)floorf((x - XMIN) * INVSTEP);
    return min(max(b, 0), NB - 1);
}
__device__ __forceinline__ unsigned long long pack2(float v) {
    unsigned long long r;
    asm("mov.b64 %0, {%1,%2};" : "=l"(r) : "f"(v), "f"(v));
    return r;
}
__device__ __forceinline__ unsigned long long fma2(unsigned long long a,
                                                   unsigned long long b,
                                                   unsigned long long c) {
    unsigned long long d;
    asm("fma.rn.f32x2 %0, %1, %2, %3;" : "=l"(d) : "l"(a), "l"(b), "l"(c));
    return d;
}
__device__ __forceinline__ void unpack2(unsigned long long v, float& lo, float& hi) {
    asm("mov.b64 {%0,%1}, %2;" : "=f"(lo), "=f"(hi) : "l"(v));
}

__device__ __forceinline__ float block_reduce_sum(float v) {
    __shared__ float warpsum[SCANTHR / 32];
    const int lane = threadIdx.x & 31;
    const int wid  = threadIdx.x >> 5;
#pragma unroll
    for (int o = 16; o > 0; o >>= 1) v += __shfl_down_sync(0xffffffffu, v, o);
    if (lane == 0) warpsum[wid] = v;
    __syncthreads();
    if (wid == 0) {
        v = (lane < (SCANTHR / 32)) ? warpsum[lane] : 0.0f;
#pragma unroll
        for (int o = 16; o > 0; o >>= 1) v += __shfl_down_sync(0xffffffffu, v, o);
    }
    return v;
}

// ---------------------------------------------------------------------------
// Prep: deterministic stable counting sort by x-bin, per (array,batch).
// Grid 16 blocks x 256 thr. blocks 0-7: shape[b]; 8-15: skel[b].
// Stability: warp w owns index chunk [w*chunk,(w+1)*chunk); within a warp,
// step order + lane order via __match_any gives index-ordered ranks.
// ---------------------------------------------------------------------------
__global__ void __launch_bounds__(PREPTHR) prep_kernel(
    const float* __restrict__ shape, const float* __restrict__ skel)
{
    __shared__ unsigned short sBin[NSHAPE];
    __shared__ unsigned short sRank[NSHAPE];
    __shared__ unsigned int   wHist[8][NB];
    __shared__ unsigned int   sCdf[NB + 1];

    const int tid  = threadIdx.x;
    const int w    = tid >> 5;
    const int lane = tid & 31;
    const int bid  = blockIdx.x;
    const bool isShape = (bid < 8);
    const int b      = isShape ? bid : bid - 8;
    const int N      = isShape ? NSHAPE : NSKEL;
    const int stride = isShape ? 6 : 3;
    const float* src = isShape ? shape + (size_t)b * NSHAPE * 6
                               : skel  + (size_t)b * NSKEL * 3;

    for (int i = tid; i < 8 * NB; i += PREPTHR) ((unsigned int*)wHist)[i] = 0;
    __syncthreads();

    const int chunk = N >> 3;           // per-warp contiguous index chunk
    const int base  = w * chunk;
    for (int s = 0; s < chunk / 32; s++) {
        const int i = base + s * 32 + lane;
        const float x = src[i * stride];
        const int bn = xbin(x);
        const unsigned mask  = __match_any_sync(0xffffffffu, bn);
        const unsigned lower = __popc(mask & ((1u << lane) - 1u));
        const unsigned prev  = wHist[w][bn];
        __syncwarp();
        sBin[i]  = (unsigned short)bn;
        sRank[i] = (unsigned short)(prev + lower);
        if (lower == 0) wHist[w][bn] = prev + __popc(mask);
        __syncwarp();
    }
    __syncthreads();

    // per-bin warp prefix (wHist -> warpBase) + totals
    if (tid < NB) {
        unsigned run = 0;
#pragma unroll
        for (int ww = 0; ww < 8; ww++) {
            const unsigned c = wHist[ww][tid];
            wHist[ww][tid] = run;
            run += c;
        }
        sCdf[tid + 1] = run;
    }
    if (tid == 0) sCdf[0] = 0;
    __syncthreads();
    if (tid == 0)
        for (int i = 1; i <= NB; i++) sCdf[i] += sCdf[i - 1];   // exclusive starts
    __syncthreads();

    // scatter: rank = cdf[bin] + warpBase[ownerWarp][bin] + intra-warp rank
    float* dx = isShape ? (float*)g_shx[b] : (float*)g_skx[b];
    float* dy = isShape ? (float*)g_shy[b] : (float*)g_sky[b];
    float* dz = isShape ? (float*)g_shz[b] : (float*)g_skz[b];
    float* dn = isShape ? (float*)g_shn[b] : (float*)g_skn[b];
    for (int i = tid; i < N; i += PREPTHR) {
        const int bn = sBin[i];
        const unsigned r = sCdf[bn] + wHist[i / chunk][bn] + sRank[i];
        const float* p = src + i * stride;
        const float x = p[0], y = p[1], z = p[2];
        dx[r] = x; dy[r] = y; dz[r] = z;
        dn[r] = fmaf(x, x, fmaf(y, y, z * z));
    }
    unsigned int* gcdf = isShape ? g_cdfSh[b] : g_cdfSk[b];
    if (tid <= NB) gcdf[tid] = sCdf[tid];
}

// ---------------------------------------------------------------------------
// Scan kernel: one thread = one sorted query. Phase A: 64 entries (128 pts)
// nearest in x-rank -> upper bound m0. Phase B: exact bin window from m0.
// Cooperative smem buffering of the block-union entry range; per-thread
// predicated scan of its own sub-range. Pruning is exact (bins outside
// [qx-rad, qx+rad] provably cannot beat d2c; rad inflated for fp rounding).
// ---------------------------------------------------------------------------
__global__ void __launch_bounds__(SCANTHR) scan_kernel(float* __restrict__ out)
{
    __shared__ float4 bufA[CHUNK];
    __shared__ float4 bufB[CHUNK];
    __shared__ unsigned int sCdfT[NB + 1];
    __shared__ int sU0, sU1;

    const int tid = threadIdx.x;
    const int bid = blockIdx.x;
    const bool side1 = (bid < S1B);

    const float2 *tX, *tY, *tZ, *tN;
    const float *qX, *qY, *qZ, *qN;
    const unsigned int* cdfT;
    int NE, qrank;
    if (side1) {                      // queries = sorted shape, tiles = skel
        const int b = bid >> 6;
        qrank = (bid & 63) * SCANTHR + tid;
        qX = (const float*)g_shx[b]; qY = (const float*)g_shy[b];
        qZ = (const float*)g_shz[b]; qN = (const float*)g_shn[b];
        tX = g_skx[b]; tY = g_sky[b]; tZ = g_skz[b]; tN = g_skn[b];
        cdfT = g_cdfSk[b]; NE = NESK;
    } else {                          // queries = sorted skel, tiles = shape
        const int r = bid - S1B;
        const int b = r >> 4;
        qrank = (r & 15) * SCANTHR + tid;
        qX = (const float*)g_skx[b]; qY = (const float*)g_sky[b];
        qZ = (const float*)g_skz[b]; qN = (const float*)g_skn[b];
        tX = g_shx[b]; tY = g_shy[b]; tZ = g_shz[b]; tN = g_shn[b];
        cdfT = g_cdfSh[b]; NE = NESH;
    }

    for (int i = tid; i <= NB; i += SCANTHR) sCdfT[i] = cdfT[i];

    const float qx = qX[qrank], qy = qY[qrank], qz = qZ[qrank];
    const float qn = qN[qrank];
    const unsigned long long cqx = pack2(-2.0f * qx);
    const unsigned long long cqy = pack2(-2.0f * qy);
    const unsigned long long cqz = pack2(-2.0f * qz);

    float mt = CUDART_INF_F;          // min over (n_j - 2 q.p_j)

    if (tid == 0) { sU0 = 0x7FFFFFFF; sU1 = 0; }
    __syncthreads();                  // also covers sCdfT fill

    // ---- phase A: 64 entries centered at my x-rank ----
    const int r0  = (int)sCdfT[xbin(qx)];
    const int ea0 = min(max(r0 / 2 - 32, 0), NE - 64);
    const int ea1 = ea0 + 64;
    atomicMin(&sU0, ea0);
    atomicMax(&sU1, ea1);
    __syncthreads();

#pragma unroll 1
    for (int phase = 0; phase < 2; phase++) {
        int e0, e1, x0, x1;
        if (phase == 0) { e0 = ea0; e1 = ea1; x0 = 0; x1 = 0; }
        else {
            const float d2c = fmaxf(qn + mt, 0.0f);
            const float rad = sqrtf(d2c) * 1.0001f;
            const int bLo = xbin(qx - rad);
            const int bHi = xbin(qx + rad);
            e0 = (int)(sCdfT[bLo] >> 1);
            e1 = (int)((sCdfT[bHi + 1] + 1u) >> 1);
            x0 = ea0; x1 = ea1;                     // already scanned
            __syncthreads();
            if (tid == 0) { sU0 = 0x7FFFFFFF; sU1 = 0; }
            __syncthreads();
            atomicMin(&sU0, e0);
            atomicMax(&sU1, e1);
            __syncthreads();
        }
        const int u0 = sU0, u1 = sU1;

        for (int cs = u0; cs < u1; cs += CHUNK) {
            const int ce = min(cs + CHUNK, u1);
            const int n  = ce - cs;
            __syncthreads();
            for (int i = tid; i < n; i += SCANTHR) {
                const float2 x2 = tX[cs + i];
                const float2 y2 = tY[cs + i];
                const float2 z2 = tZ[cs + i];
                const float2 n2 = tN[cs + i];
                bufA[i] = make_float4(x2.x, x2.y, y2.x, y2.y);
                bufB[i] = make_float4(z2.x, z2.y, n2.x, n2.y);
            }
            __syncthreads();

            const int l0 = max(e0, cs), l1 = min(e1, ce);
            const ulonglong2* pA = reinterpret_cast<const ulonglong2*>(bufA);
            const ulonglong2* pB = reinterpret_cast<const ulonglong2*>(bufB);
#pragma unroll 4
            for (int e = l0; e < l1; e++) {
                if (e >= x0 && e < x1) continue;
                const ulonglong2 A = pA[e - cs];    // (x-pair, y-pair)
                const ulonglong2 B = pB[e - cs];    // (z-pair, n-pair)
                unsigned long long t = fma2(cqx, A.x, B.y);
                t = fma2(cqy, A.y, t);
                t = fma2(cqz, B.x, t);
                float lo, hi;
                unpack2(t, lo, hi);
                mt = fminf(mt, fminf(lo, hi));
            }
        }
        __syncthreads();
    }

    // ---- finalize ----
    const float d2 = fmaxf(qn + mt, 0.0f);
    const float s  = block_reduce_sum(sqrtf(d2));
    if (tid == 0) {
        atomicAdd(&g_accum, s);
        __threadfence();
        if (atomicAdd(&g_done, 1u) == NBLK - 1) {
            out[0] = atomicExch(&g_accum, 0.0f) * 1.0e-4f;
            g_done = 0;
        }
    }
}

// ---------------------------------------------------------------------------
extern "C" void kernel_launch(void* const* d_in, const int* in_sizes, int n_in,
                              void* d_out, int out_size)
{
    const float* shape = (const float*)d_in[0];  // (8, 8192, 6) fp32
    const float* skel  = (const float*)d_in[1];  // (8, 2048, 3) fp32
    prep_kernel<<<16, PREPTHR>>>(shape, skel);
    scan_kernel<<<NBLK, SCANTHR>>>((float*)d_out);
}